// round 9
// baseline (speedup 1.0000x reference)
#include <cuda_runtime.h>
#include <cuda_bf16.h>
#include <math.h>

#define NLEVELS 16
#define TBL     (1u << 19)
#define NPTS    (64 * 64 * 64)

constexpr double SCALE_ = 1.447269237440378;

__host__ __device__ constexpr int res_of(int l) {
    double r = 16.0;
    for (int i = 0; i < l; ++i) r *= SCALE_;
    return (int)(r + 1e-6);
}

// Gather all 16 levels for one point; writes 16 bf16x2 encodings.
__device__ __forceinline__
void gather_point(const float* __restrict__ pts, int i,
                  const float* __restrict__ table,
                  __nv_bfloat162* __restrict__ enc2)
{
    const float px = __ldg(pts + 3 * i + 0);
    const float py = __ldg(pts + 3 * i + 1);
    const float pz = __ldg(pts + 3 * i + 2);

    constexpr int RESA[NLEVELS] = {
        res_of(0),  res_of(1),  res_of(2),  res_of(3),
        res_of(4),  res_of(5),  res_of(6),  res_of(7),
        res_of(8),  res_of(9),  res_of(10), res_of(11),
        res_of(12), res_of(13), res_of(14), res_of(15)
    };

#pragma unroll
    for (int l = 0; l < NLEVELS; ++l) {
        const int res = RESA[l];
        const bool dense = ((long long)(res + 1) * (res + 1) * (res + 1) <= (long long)TBL);

        const float fres = (float)res;
        const float x = px * fres, y = py * fres, z = pz * fres;
        const float fx = floorf(x), fy = floorf(y), fz = floorf(z);
        const float tx = x - fx, ty = y - fy, tz = z - fz;
        const unsigned cx = (unsigned)fx, cy = (unsigned)fy, cz = (unsigned)fz;

        const float2* tab = (const float2*)table + (size_t)l * TBL;

        unsigned iA[4], iB[4];
#pragma unroll
        for (int c = 0; c < 4; ++c) {
            const unsigned Y = cy + ((c >> 1) & 1u);
            const unsigned Z = cz + (c & 1u);
            if (dense) {
                const unsigned r1 = (unsigned)(res + 1);
                const unsigned b = r1 * (Y + r1 * Z);
                iA[c] = (cx + b) & (TBL - 1u);
                iB[c] = (cx + 1u + b) & (TBL - 1u);
            } else {
                const unsigned h = (Y * 2654435761u) ^ (Z * 805459861u);
                iA[c] = (cx ^ h) & (TBL - 1u);
                iB[c] = ((cx + 1u) ^ h) & (TBL - 1u);
            }
        }

        float4 v[4];
#pragma unroll
        for (int c = 0; c < 4; ++c)
            v[c] = __ldg((const float4*)tab + (iA[c] >> 1));

        float2 b64[4];
        bool cont[4];
#pragma unroll
        for (int c = 0; c < 4; ++c) {
            cont[c] = ((iA[c] >> 1) == (iB[c] >> 1));
            if (!cont[c]) b64[c] = __ldg(tab + iB[c]);
        }

        float e0 = 0.f, e1 = 0.f;
#pragma unroll
        for (int c = 0; c < 4; ++c) {
            const float2 lo = make_float2(v[c].x, v[c].y);
            const float2 hi = make_float2(v[c].z, v[c].w);
            const float2 tA = (iA[c] & 1u) ? hi : lo;
            const float2 tBc = (iB[c] & 1u) ? hi : lo;
            const float2 tB = cont[c] ? tBc : b64[c];
            const float wyz = (((c >> 1) & 1) ? ty : 1.f - ty) *
                              ((c & 1) ? tz : 1.f - tz);
            const float wA = (1.f - tx) * wyz;
            const float wB = tx * wyz;
            e0 = fmaf(wA, tA.x, fmaf(wB, tB.x, e0));
            e1 = fmaf(wA, tA.y, fmaf(wB, tB.y, e1));
        }
        enc2[l] = __floats2bfloat162_rn(e0, e1);
    }
}

#define STG_STRIDE 17   // floats; odd stride -> conflict-free 32-bit staging

__global__ __launch_bounds__(256, 4)
void hashgrid_mlp_kernel(const float* __restrict__ pts,
                         const float* __restrict__ table,
                         const float* __restrict__ w1,
                         const float* __restrict__ w2,
                         float* __restrict__ out)
{
    __shared__ __nv_bfloat162 sw1p[64 * 16];   // w1 packed bf16x2
    __shared__ float sw2[64];
    __shared__ unsigned sstage[256 * STG_STRIDE];  // point-A encodings

    const int tid = threadIdx.x;
    for (int k = tid; k < 64 * 16; k += 256)
        sw1p[k] = __floats2bfloat162_rn(w1[2 * k], w1[2 * k + 1]);
    if (tid < 64) sw2[tid] = w2[tid];
    __syncthreads();

    const int i0 = blockIdx.x * 512 + tid;      // point A
    const int i1 = i0 + 256;                    // point B

    // ---- phase A: gather point A, stage encoding to smem ----
    {
        __nv_bfloat162 encA[NLEVELS];
        gather_point(pts, i0, table, encA);
        unsigned* st = sstage + tid * STG_STRIDE;
#pragma unroll
        for (int l = 0; l < NLEVELS; ++l)
            st[l] = *reinterpret_cast<unsigned*>(&encA[l]);
    }

    // ---- phase B: gather point B, keep in regs ----
    __nv_bfloat162 encB[NLEVELS];
    gather_point(pts, i1, table, encB);

    // reload point-A encoding
    __nv_bfloat162 encA[NLEVELS];
    {
        const unsigned* st = sstage + tid * STG_STRIDE;
#pragma unroll
        for (int l = 0; l < NLEVELS; ++l) {
            const unsigned u = st[l];
            encA[l] = *reinterpret_cast<const __nv_bfloat162*>(&u);
        }
    }

    // ---- MLP for both points; each weight row loaded once ----
    float accA = 0.f, accB = 0.f;
#pragma unroll
    for (int j = 0; j < 64; ++j) {
        __nv_bfloat162 hA = __floats2bfloat162_rn(0.f, 0.f);
        __nv_bfloat162 hB = __floats2bfloat162_rn(0.f, 0.f);
        const float4* row = (const float4*)(sw1p + j * 16);
#pragma unroll
        for (int q = 0; q < 4; ++q) {
            float4 vf = row[q];
            const __nv_bfloat162 w0 = *reinterpret_cast<const __nv_bfloat162*>(&vf.x);
            const __nv_bfloat162 w1b = *reinterpret_cast<const __nv_bfloat162*>(&vf.y);
            const __nv_bfloat162 w2b = *reinterpret_cast<const __nv_bfloat162*>(&vf.z);
            const __nv_bfloat162 w3b = *reinterpret_cast<const __nv_bfloat162*>(&vf.w);
            hA = __hfma2(encA[4 * q + 0], w0, hA);
            hA = __hfma2(encA[4 * q + 1], w1b, hA);
            hA = __hfma2(encA[4 * q + 2], w2b, hA);
            hA = __hfma2(encA[4 * q + 3], w3b, hA);
            hB = __hfma2(encB[4 * q + 0], w0, hB);
            hB = __hfma2(encB[4 * q + 1], w1b, hB);
            hB = __hfma2(encB[4 * q + 2], w2b, hB);
            hB = __hfma2(encB[4 * q + 3], w3b, hB);
        }
        float ha = __low2float(hA) + __high2float(hA);
        float hb = __low2float(hB) + __high2float(hB);
        ha = fmaxf(ha, 0.f);
        hb = fmaxf(hb, 0.f);
        const float w2j = sw2[j];
        accA = fmaf(ha, w2j, accA);
        accB = fmaf(hb, w2j, accB);
    }

    out[i0] = __fdividef(1.f, 1.f + __expf(-accA));
    out[i1] = __fdividef(1.f, 1.f + __expf(-accB));
}

extern "C" void kernel_launch(void* const* d_in, const int* in_sizes, int n_in,
                              void* d_out, int out_size)
{
    const float* pts   = (const float*)d_in[0];   // [N,3]
    const float* table = (const float*)d_in[1];   // [16, 2^19, 2]
    const float* w1    = (const float*)d_in[2];   // [64, 32]
    const float* w2    = (const float*)d_in[3];   // [1, 64]
    float* out = (float*)d_out;

    hashgrid_mlp_kernel<<<NPTS / 512, 256>>>(pts, table, w1, w2, out);
}

// round 12
// speedup vs baseline: 1.1356x; 1.1356x over previous
#include <cuda_runtime.h>
#include <cuda_bf16.h>

#define NLEVELS 16
#define TBL     (1u << 19)
#define NPTS    (64 * 64 * 64)

constexpr double SCALE_ = 1.447269237440378;

__host__ __device__ constexpr int res_of(int l) {
    double r = 16.0;
    for (int i = 0; i < l; ++i) r *= SCALE_;
    return (int)(r + 1e-6);
}

#define STG_STRIDE 17   // odd stride -> conflict-free 32-bit staging

__global__ __launch_bounds__(256, 5)
void hashgrid_mlp_kernel(const float* __restrict__ pts,
                         const float* __restrict__ table,
                         const float* __restrict__ w1,
                         const float* __restrict__ w2,
                         float* __restrict__ out)
{
    __shared__ __nv_bfloat162 sw1p[64 * 16];       // w1 packed bf16x2 (2 KB)
    __shared__ float sw2[64];
    __shared__ unsigned sstage[256 * STG_STRIDE];  // per-thread encodings (17.4 KB)

    const int tid = threadIdx.x;
    for (int k = tid; k < 64 * 16; k += 256)
        sw1p[k] = __floats2bfloat162_rn(w1[2 * k], w1[2 * k + 1]);
    if (tid < 64) sw2[tid] = w2[tid];
    __syncthreads();

    const int i = blockIdx.x * 256 + tid;

    const float px = __ldg(pts + 3 * i + 0);
    const float py = __ldg(pts + 3 * i + 1);
    const float pz = __ldg(pts + 3 * i + 2);

    constexpr int RESA[NLEVELS] = {
        res_of(0),  res_of(1),  res_of(2),  res_of(3),
        res_of(4),  res_of(5),  res_of(6),  res_of(7),
        res_of(8),  res_of(9),  res_of(10), res_of(11),
        res_of(12), res_of(13), res_of(14), res_of(15)
    };

    unsigned* st = sstage + tid * STG_STRIDE;

#pragma unroll
    for (int l = 0; l < NLEVELS; ++l) {
        const int res = RESA[l];
        const bool dense = ((long long)(res + 1) * (res + 1) * (res + 1) <= (long long)TBL);

        const float fres = (float)res;
        const float x = px * fres, y = py * fres, z = pz * fres;
        const float fx = floorf(x), fy = floorf(y), fz = floorf(z);
        const float tx = x - fx, ty = y - fy, tz = z - fz;
        const unsigned cx = (unsigned)fx, cy = (unsigned)fy, cz = (unsigned)fz;

        const float2* tab = (const float2*)table + (size_t)l * TBL;

        // 4 X-pairs: corners (cx,Y,Z) and (cx+1,Y,Z) for the 4 (Y,Z) combos.
        unsigned iA[4], iB[4];
#pragma unroll
        for (int c = 0; c < 4; ++c) {
            const unsigned Y = cy + ((c >> 1) & 1u);
            const unsigned Z = cz + (c & 1u);
            if (dense) {
                const unsigned r1 = (unsigned)(res + 1);
                const unsigned b = r1 * (Y + r1 * Z);
                iA[c] = (cx + b) & (TBL - 1u);
                iB[c] = (cx + 1u + b) & (TBL - 1u);
            } else {
                const unsigned h = (Y * 2654435761u) ^ (Z * 805459861u);
                iA[c] = (cx ^ h) & (TBL - 1u);
                iB[c] = ((cx + 1u) ^ h) & (TBL - 1u);
            }
        }

        // Aligned 16B block holding iA (delivers iB too when pair contained).
        float4 v[4];
#pragma unroll
        for (int c = 0; c < 4; ++c)
            v[c] = __ldg((const float4*)tab + (iA[c] >> 1));

        float2 b64[4];
        bool cont[4];
#pragma unroll
        for (int c = 0; c < 4; ++c) {
            cont[c] = ((iA[c] >> 1) == (iB[c] >> 1));
            if (!cont[c]) b64[c] = __ldg(tab + iB[c]);
        }

        float e0 = 0.f, e1 = 0.f;
#pragma unroll
        for (int c = 0; c < 4; ++c) {
            const float2 lo = make_float2(v[c].x, v[c].y);
            const float2 hi = make_float2(v[c].z, v[c].w);
            const float2 tA = (iA[c] & 1u) ? hi : lo;
            const float2 tBc = (iB[c] & 1u) ? hi : lo;
            const float2 tB = cont[c] ? tBc : b64[c];
            const float wyz = (((c >> 1) & 1) ? ty : 1.f - ty) *
                              ((c & 1) ? tz : 1.f - tz);
            const float wA = (1.f - tx) * wyz;
            const float wB = tx * wyz;
            e0 = fmaf(wA, tA.x, fmaf(wB, tB.x, e0));
            e1 = fmaf(wA, tA.y, fmaf(wB, tB.y, e1));
        }
        // stream encoding to smem; keeps enc out of gather-phase registers
        const __nv_bfloat162 p = __floats2bfloat162_rn(e0, e1);
        st[l] = *reinterpret_cast<const unsigned*>(&p);
    }

    // reload all 16 encodings for the MLP
    __nv_bfloat162 enc2[NLEVELS];
#pragma unroll
    for (int l = 0; l < NLEVELS; ++l) {
        const unsigned u = st[l];
        enc2[l] = *reinterpret_cast<const __nv_bfloat162*>(&u);
    }

    // ---- tiny MLP in bf16x2: 4 LDS.128 + 16 HFMA2 per hidden unit ----
    float acc = 0.f;
#pragma unroll
    for (int j = 0; j < 64; ++j) {
        __nv_bfloat162 hacc = __floats2bfloat162_rn(0.f, 0.f);
        const float4* row = (const float4*)(sw1p + j * 16);
#pragma unroll
        for (int q = 0; q < 4; ++q) {
            float4 vf = row[q];
            const __nv_bfloat162 w0 = *reinterpret_cast<const __nv_bfloat162*>(&vf.x);
            const __nv_bfloat162 w1b = *reinterpret_cast<const __nv_bfloat162*>(&vf.y);
            const __nv_bfloat162 w2b = *reinterpret_cast<const __nv_bfloat162*>(&vf.z);
            const __nv_bfloat162 w3b = *reinterpret_cast<const __nv_bfloat162*>(&vf.w);
            hacc = __hfma2(enc2[4 * q + 0], w0, hacc);
            hacc = __hfma2(enc2[4 * q + 1], w1b, hacc);
            hacc = __hfma2(enc2[4 * q + 2], w2b, hacc);
            hacc = __hfma2(enc2[4 * q + 3], w3b, hacc);
        }
        float h = __low2float(hacc) + __high2float(hacc);
        h = fmaxf(h, 0.f);
        acc = fmaf(h, sw2[j], acc);
    }

    out[i] = __fdividef(1.f, 1.f + __expf(-acc));
}

extern "C" void kernel_launch(void* const* d_in, const int* in_sizes, int n_in,
                              void* d_out, int out_size)
{
    const float* pts   = (const float*)d_in[0];   // [N,3]
    const float* table = (const float*)d_in[1];   // [16, 2^19, 2]
    const float* w1    = (const float*)d_in[2];   // [64, 32]
    const float* w2    = (const float*)d_in[3];   // [1, 64]
    float* out = (float*)d_out;

    hashgrid_mlp_kernel<<<NPTS / 256, 256>>>(pts, table, w1, w2, out);
}

// round 13
// speedup vs baseline: 1.2723x; 1.1203x over previous
#include <cuda_runtime.h>
#include <cuda_bf16.h>

#define NLEVELS 16
#define TBL     (1u << 19)
#define NPTS    (64 * 64 * 64)

constexpr double SCALE_ = 1.447269237440378;

__host__ __device__ constexpr int res_of(int l) {
    double r = 16.0;
    for (int i = 0; i < l; ++i) r *= SCALE_;
    return (int)(r + 1e-6);
}

#define ENC_ROW_BYTES 80                      // 64B data + 16B pad (conflict-free)
#define ENC_WARP_BYTES (32 * ENC_ROW_BYTES)   // 2560B per warp
#define W1T_ROW 72                            // bf16 units per row (64 + 8 pad)

__device__ __forceinline__ unsigned smem_u32(const void* p) {
    unsigned a;
    asm("{ .reg .u64 t; cvta.to.shared.u64 t, %1; cvt.u32.u64 %0, t; }"
        : "=r"(a) : "l"(p));
    return a;
}

__global__ __launch_bounds__(256, 4)
void hashgrid_mlp_kernel(const float* __restrict__ pts,
                         const float* __restrict__ table,
                         const float* __restrict__ w1,
                         const float* __restrict__ w2,
                         float* __restrict__ out)
{
    __shared__ __align__(16) unsigned char senc[8 * ENC_WARP_BYTES];  // 20 KB
    __shared__ __nv_bfloat16 sw1t[32 * W1T_ROW];                      // w1^T, 4.5 KB
    __shared__ float sw2[64];
    __shared__ float sacc[256];

    const int tid = threadIdx.x;
    // stage w1 transposed: sw1t[k][j] = bf16(w1[j][k])
    for (int idx = tid; idx < 64 * 32; idx += 256) {
        const int j = idx >> 5, k = idx & 31;
        sw1t[k * W1T_ROW + j] = __float2bfloat16(w1[idx]);
    }
    if (tid < 64) sw2[tid] = w2[tid];
    __syncthreads();

    const int i = blockIdx.x * 256 + tid;
    const int lane = tid & 31, wid = tid >> 5;

    const float px = __ldg(pts + 3 * i + 0);
    const float py = __ldg(pts + 3 * i + 1);
    const float pz = __ldg(pts + 3 * i + 2);

    unsigned enc2[NLEVELS];   // bf16x2 per level

    constexpr int RESA[NLEVELS] = {
        res_of(0),  res_of(1),  res_of(2),  res_of(3),
        res_of(4),  res_of(5),  res_of(6),  res_of(7),
        res_of(8),  res_of(9),  res_of(10), res_of(11),
        res_of(12), res_of(13), res_of(14), res_of(15)
    };

#pragma unroll
    for (int l = 0; l < NLEVELS; ++l) {
        const int res = RESA[l];
        const bool dense = ((long long)(res + 1) * (res + 1) * (res + 1) <= (long long)TBL);

        const float fres = (float)res;
        const float x = px * fres, y = py * fres, z = pz * fres;
        const float fx = floorf(x), fy = floorf(y), fz = floorf(z);
        const float tx = x - fx, ty = y - fy, tz = z - fz;
        const unsigned cx = (unsigned)fx, cy = (unsigned)fy, cz = (unsigned)fz;

        const float2* tab = (const float2*)table + (size_t)l * TBL;

        unsigned iA[4], iB[4];
#pragma unroll
        for (int c = 0; c < 4; ++c) {
            const unsigned Y = cy + ((c >> 1) & 1u);
            const unsigned Z = cz + (c & 1u);
            if (dense) {
                const unsigned r1 = (unsigned)(res + 1);
                const unsigned b = r1 * (Y + r1 * Z);
                iA[c] = (cx + b) & (TBL - 1u);
                iB[c] = (cx + 1u + b) & (TBL - 1u);
            } else {
                const unsigned h = (Y * 2654435761u) ^ (Z * 805459861u);
                iA[c] = (cx ^ h) & (TBL - 1u);
                iB[c] = ((cx + 1u) ^ h) & (TBL - 1u);
            }
        }

        float4 v[4];
#pragma unroll
        for (int c = 0; c < 4; ++c)
            v[c] = __ldg((const float4*)tab + (iA[c] >> 1));

        float2 b64[4];
        bool cont[4];
#pragma unroll
        for (int c = 0; c < 4; ++c) {
            cont[c] = ((iA[c] >> 1) == (iB[c] >> 1));
            if (!cont[c]) b64[c] = __ldg(tab + iB[c]);
        }

        float e0 = 0.f, e1 = 0.f;
#pragma unroll
        for (int c = 0; c < 4; ++c) {
            const float2 lo = make_float2(v[c].x, v[c].y);
            const float2 hi = make_float2(v[c].z, v[c].w);
            const float2 tA = (iA[c] & 1u) ? hi : lo;
            const float2 tBc = (iB[c] & 1u) ? hi : lo;
            const float2 tB = cont[c] ? tBc : b64[c];
            const float wyz = (((c >> 1) & 1) ? ty : 1.f - ty) *
                              ((c & 1) ? tz : 1.f - tz);
            const float wA = (1.f - tx) * wyz;
            const float wB = tx * wyz;
            e0 = fmaf(wA, tA.x, fmaf(wB, tB.x, e0));
            e1 = fmaf(wA, tA.y, fmaf(wB, tB.y, e1));
        }
        const __nv_bfloat162 p = __floats2bfloat162_rn(e0, e1);
        enc2[l] = *reinterpret_cast<const unsigned*>(&p);
    }

    // ---- write encoding row to smem (4 STS.128, conflict-free at stride 80) ----
    unsigned char* myrow = senc + wid * ENC_WARP_BYTES + lane * ENC_ROW_BYTES;
#pragma unroll
    for (int q = 0; q < 4; ++q) {
        uint4 w = make_uint4(enc2[4 * q + 0], enc2[4 * q + 1],
                             enc2[4 * q + 2], enc2[4 * q + 3]);
        *reinterpret_cast<uint4*>(myrow + 16 * q) = w;
    }
    __syncwarp();

    // ---- tensor-core MLP: C[32x64] = A[32x32] @ w1^T, relu, dot w2 ----
    const unsigned encb = smem_u32(senc) + wid * ENC_WARP_BYTES;
    const unsigned w1tb = smem_u32(sw1t);
    const int g = lane >> 2, t = lane & 3;

    // A fragments: [mt][kt] -> 4 regs each
    unsigned a[2][2][4];
    {
        const int m = lane >> 3;                 // 0..3
        const int rown = ((m & 1) << 3) + (lane & 7);
        const int seg = m >> 1;                  // 0..1
#pragma unroll
        for (int mt = 0; mt < 2; ++mt)
#pragma unroll
            for (int kt = 0; kt < 2; ++kt) {
                const unsigned addr = encb + (mt * 16 + rown) * ENC_ROW_BYTES
                                    + kt * 32 + seg * 16;
                asm volatile("ldmatrix.sync.aligned.m8n8.x4.shared.b16 "
                             "{%0,%1,%2,%3}, [%4];"
                             : "=r"(a[mt][kt][0]), "=r"(a[mt][kt][1]),
                               "=r"(a[mt][kt][2]), "=r"(a[mt][kt][3])
                             : "r"(addr));
            }
    }

    float acc0 = 0.f, acc1 = 0.f, acc2 = 0.f, acc3 = 0.f;
    const int brow = (lane & 7) + ((lane >> 3) & 1) * 8;   // 0..15 (lanes 0-15 used)

#pragma unroll
    for (int nt = 0; nt < 8; ++nt) {
        // B fragments for this n-tile, both k-halves
        unsigned b0[2], b1[2];
#pragma unroll
        for (int kt = 0; kt < 2; ++kt) {
            const unsigned baddr = w1tb + (kt * 16 + brow) * (W1T_ROW * 2) + nt * 16;
            asm volatile("ldmatrix.sync.aligned.m8n8.x2.trans.shared.b16 "
                         "{%0,%1}, [%2];"
                         : "=r"(b0[kt]), "=r"(b1[kt]) : "r"(baddr));
        }
        const float2 w2p = *reinterpret_cast<const float2*>(sw2 + nt * 8 + 2 * t);
#pragma unroll
        for (int mt = 0; mt < 2; ++mt) {
            float c0 = 0.f, c1 = 0.f, c2 = 0.f, c3 = 0.f;
#pragma unroll
            for (int kt = 0; kt < 2; ++kt) {
                asm volatile(
                    "mma.sync.aligned.m16n8k16.row.col.f32.bf16.bf16.f32 "
                    "{%0,%1,%2,%3}, {%4,%5,%6,%7}, {%8,%9}, {%0,%1,%2,%3};"
                    : "+f"(c0), "+f"(c1), "+f"(c2), "+f"(c3)
                    : "r"(a[mt][kt][0]), "r"(a[mt][kt][1]),
                      "r"(a[mt][kt][2]), "r"(a[mt][kt][3]),
                      "r"(b0[kt]), "r"(b1[kt]));
            }
            c0 = fmaxf(c0, 0.f); c1 = fmaxf(c1, 0.f);
            c2 = fmaxf(c2, 0.f); c3 = fmaxf(c3, 0.f);
            if (mt == 0) {
                acc0 = fmaf(c0, w2p.x, fmaf(c1, w2p.y, acc0));   // row g
                acc1 = fmaf(c2, w2p.x, fmaf(c3, w2p.y, acc1));   // row g+8
            } else {
                acc2 = fmaf(c0, w2p.x, fmaf(c1, w2p.y, acc2));   // row 16+g
                acc3 = fmaf(c2, w2p.x, fmaf(c3, w2p.y, acc3));   // row 24+g
            }
        }
    }

    // reduce across the 4 t-lanes of each group
#pragma unroll
    for (int s = 1; s < 4; s <<= 1) {
        acc0 += __shfl_xor_sync(~0u, acc0, s);
        acc1 += __shfl_xor_sync(~0u, acc1, s);
        acc2 += __shfl_xor_sync(~0u, acc2, s);
        acc3 += __shfl_xor_sync(~0u, acc3, s);
    }
    if (t == 0) {
        float* sa = sacc + wid * 32;
        sa[g]      = acc0;
        sa[g + 8]  = acc1;
        sa[g + 16] = acc2;
        sa[g + 24] = acc3;
    }
    __syncwarp();

    const float accv = sacc[wid * 32 + lane];
    out[i] = __fdividef(1.f, 1.f + __expf(-accv));
}

extern "C" void kernel_launch(void* const* d_in, const int* in_sizes, int n_in,
                              void* d_out, int out_size)
{
    const float* pts   = (const float*)d_in[0];   // [N,3]
    const float* table = (const float*)d_in[1];   // [16, 2^19, 2]
    const float* w1    = (const float*)d_in[2];   // [64, 32]
    const float* w2    = (const float*)d_in[3];   // [1, 64]
    float* out = (float*)d_out;

    hashgrid_mlp_kernel<<<NPTS / 256, 256>>>(pts, table, w1, w2, out);
}